// round 3
// baseline (speedup 1.0000x reference)
#include <cuda_runtime.h>

// Renderer_45612552684068 — fp32 baseline, round 3.
// Fix: __align__(16) on static shared arrays used via float4 casts
// (conv2's w_s landed at an 8-mod-16 byte offset -> misaligned LDS.128).

static constexpr int NB   = 4;
static constexpr int NH   = 512;
static constexpr int NW   = 512;
static constexpr int HID  = 128;
static constexpr int CIN  = 29;   // DIM - 3
static constexpr int C1C  = 64;
static constexpr int C2C  = 128;

// scratch (statically allocated device globals; no cudaMalloc anywhere)
__device__ __align__(16) float g_x  [NB * CIN * NH * NW];
__device__ __align__(16) float g_rgb[NB * 3   * NH * NW];
__device__ __align__(16) float g_e1 [NB * C1C * NH * NW];
__device__ __align__(16) float g_d  [NB * C2C * (NH/2) * (NW/2)];
__device__ __align__(16) float g_m  [NB * C1C * NH * NW];

// ---------------------------------------------------------------------------
// MLP kernel: 128 pixels per block, 256 threads.
static constexpr int MLP_SMEM_FLOATS = 16384 + 16512 + 16384 + 1024 + 128 + 128;
static constexpr int MLP_SMEM_BYTES  = MLP_SMEM_FLOATS * 4;

__global__ __launch_bounds__(256, 1)
void mlp_kernel(const float* __restrict__ zbuf, const float* __restrict__ ray,
                const float* __restrict__ w0, const float* __restrict__ b0,
                const float* __restrict__ w1, const float* __restrict__ b1,
                const float* __restrict__ w2, const float* __restrict__ b2)
{
    extern __shared__ float sm[];
    float* sh_h1  = sm;                       // [k*128 + p]         16384
    float* sh_h2  = sh_h1 + 16384;            // [k*129 + p]         16512
    float* sh_w   = sh_h2 + 16512;            // w1 then w2          16384
    float* sh_fin = sh_w  + 16384;            // [p*8 + i]           1024
    float* sh_z   = sh_fin + 1024;
    float* sh_b1  = sh_z + 128;

    const int tid   = threadIdx.x;
    const int pbase = blockIdx.x * 128;

    // stage w1 (64KB) + b1 — scalar loads (input alignment unknown)
    {
        #pragma unroll 8
        for (int t = tid; t < 16384; t += 256) sh_w[t] = w1[t];
        if (tid < 128) sh_b1[tid] = b1[tid];
    }

    // phase 0: fin
    if (tid < 128) {
        int pix = pbase + tid;
        int b = pix >> 18;
        int y = (pix >> 9) & 511;
        int x = pix & 511;
        int pi = (b * NH + y) * NW + x;
        float z = zbuf[pi];
        const float* r = ray + pi * 7;
        float t  = z / r[6];
        float d0 = r[3], d1 = r[4], d2 = r[5];
        sh_fin[tid * 8 + 0] = fmaf(d0, t, r[0]);
        sh_fin[tid * 8 + 1] = fmaf(d1, t, r[1]);
        sh_fin[tid * 8 + 2] = fmaf(d2, t, r[2]);
        sh_fin[tid * 8 + 3] = d0;
        sh_fin[tid * 8 + 4] = d1;
        sh_fin[tid * 8 + 5] = d2;
        sh_z[tid] = z;
    }
    __syncthreads();

    // phase 1: h1 = relu(fin@w0 + b0)  -> sh_h1[o][p]
    {
        const int p  = tid & 127;
        const int ob = (tid >> 7) * 64;
        float f0 = sh_fin[p*8+0], f1 = sh_fin[p*8+1], f2 = sh_fin[p*8+2];
        float f3 = sh_fin[p*8+3], f4 = sh_fin[p*8+4], f5 = sh_fin[p*8+5];
        #pragma unroll 8
        for (int o = ob; o < ob + 64; o++) {
            float acc = b0[o];
            acc = fmaf(f0, w0[0*HID + o], acc);
            acc = fmaf(f1, w0[1*HID + o], acc);
            acc = fmaf(f2, w0[2*HID + o], acc);
            acc = fmaf(f3, w0[3*HID + o], acc);
            acc = fmaf(f4, w0[4*HID + o], acc);
            acc = fmaf(f5, w0[5*HID + o], acc);
            sh_h1[o * 128 + p] = fmaxf(acc, 0.f);
        }
    }
    __syncthreads();

    // phase 2: h2 = relu(h1@w1 + b1); 128x128x128 GEMM, 8x8 micro-tiles
    const int tx = tid & 15;    // output dim
    const int ty = tid >> 4;    // pixel dim
    {
        float c[8][8];
        #pragma unroll
        for (int i = 0; i < 8; i++)
            #pragma unroll
            for (int j = 0; j < 8; j++) c[i][j] = 0.f;

        #pragma unroll 2
        for (int k = 0; k < 128; k++) {
            float a[8], bv[8];
            float4 t0 = *(const float4*)&sh_h1[k*128 + ty*8];
            float4 t1 = *(const float4*)&sh_h1[k*128 + ty*8 + 4];
            a[0]=t0.x; a[1]=t0.y; a[2]=t0.z; a[3]=t0.w;
            a[4]=t1.x; a[5]=t1.y; a[6]=t1.z; a[7]=t1.w;
            float4 u0 = *(const float4*)&sh_w[k*128 + tx*8];
            float4 u1 = *(const float4*)&sh_w[k*128 + tx*8 + 4];
            bv[0]=u0.x; bv[1]=u0.y; bv[2]=u0.z; bv[3]=u0.w;
            bv[4]=u1.x; bv[5]=u1.y; bv[6]=u1.z; bv[7]=u1.w;
            #pragma unroll
            for (int i = 0; i < 8; i++)
                #pragma unroll
                for (int j = 0; j < 8; j++)
                    c[i][j] = fmaf(a[i], bv[j], c[i][j]);
        }
        // epilogue: transpose-store to sh_h2[o][p]
        #pragma unroll
        for (int j = 0; j < 8; j++) {
            float bb = sh_b1[tx*8 + j];
            #pragma unroll
            for (int i = 0; i < 8; i++)
                sh_h2[(tx*8 + j) * 129 + (ty*8 + i)] = fmaxf(c[i][j] + bb, 0.f);
        }
    }
    __syncthreads();

    // stage w2 (128x32) over w1's smem — scalar loads
    {
        for (int t = tid; t < 128*32; t += 256) sh_w[t] = w2[t];
    }
    __syncthreads();

    // phase 3: feat = h2@w2 + b2 ; phase 4: mask + NCHW scatter
    {
        const int p  = tid & 127;
        const int ob = (tid >> 7) * 16;
        float f[16];
        #pragma unroll
        for (int j = 0; j < 16; j++) f[j] = b2[ob + j];
        for (int k = 0; k < 128; k++) {
            float a = sh_h2[k * 129 + p];
            #pragma unroll
            for (int g = 0; g < 4; g++) {
                float4 wv = *(const float4*)&sh_w[k*32 + ob + g*4];
                f[g*4+0] = fmaf(a, wv.x, f[g*4+0]);
                f[g*4+1] = fmaf(a, wv.y, f[g*4+1]);
                f[g*4+2] = fmaf(a, wv.z, f[g*4+2]);
                f[g*4+3] = fmaf(a, wv.w, f[g*4+3]);
            }
        }
        int pix = pbase + p;
        int b = pix >> 18;
        int y = (pix >> 9) & 511;
        int x = pix & 511;
        bool mask = sh_z[p] > 0.f;
        #pragma unroll
        for (int j = 0; j < 16; j++) {
            int cch = ob + j;
            float v = mask ? f[j] : 1.0f;
            if (cch < CIN)
                g_x[((b*CIN + cch) * NH + y) * NW + x] = v;
            else
                g_rgb[((b*3 + (cch - CIN)) * NH + y) * NW + x] = v;
        }
    }
}

// ---------------------------------------------------------------------------
// conv1: 29->64, 3x3, SAME (centered), relu. out tile 32x8, 64 cout.
__global__ __launch_bounds__(256, 2)
void conv1_kernel(const float* __restrict__ wk)
{
    __shared__ __align__(16) float in_s[4][10][35];
    __shared__ __align__(16) float w_s[4][9][64];
    const int tid = threadIdx.x;
    const int xg = tid & 3, yy = (tid >> 2) & 7, cg = tid >> 5;
    const int x0 = blockIdx.x * 32, y0 = blockIdx.y * 8, b = blockIdx.z;

    float acc[8][8];
    #pragma unroll
    for (int j = 0; j < 8; j++)
        #pragma unroll
        for (int i = 0; i < 8; i++) acc[j][i] = 0.f;

    for (int c0 = 0; c0 < CIN; c0 += 4) {
        const int cc = min(4, CIN - c0);
        __syncthreads();
        for (int t = tid; t < cc * 340; t += 256) {
            int ci = t / 340, rem = t - ci * 340;
            int rr = rem / 34, cx = rem - rr * 34;
            int iy = y0 - 1 + rr, ix = x0 - 1 + cx;
            float v = 0.f;
            if (iy >= 0 && iy < NH && ix >= 0 && ix < NW)
                v = g_x[((b*CIN + c0 + ci) * NH + iy) * NW + ix];
            in_s[ci][rr][cx] = v;
        }
        for (int t = tid; t < cc * 576; t += 256) {
            int co = t & 63, tap = (t >> 6) % 9, ci = t / 576;
            w_s[ci][tap][co] = wk[(co * CIN + c0 + ci) * 9 + tap];
        }
        __syncthreads();
        for (int ci = 0; ci < cc; ci++) {
            #pragma unroll
            for (int kh = 0; kh < 3; kh++) {
                float a[10];
                #pragma unroll
                for (int c = 0; c < 10; c++) a[c] = in_s[ci][yy + kh][xg*8 + c];
                #pragma unroll
                for (int kw = 0; kw < 3; kw++) {
                    int tap = kh*3 + kw;
                    float4 v0 = *(const float4*)&w_s[ci][tap][cg*8];
                    float4 v1 = *(const float4*)&w_s[ci][tap][cg*8 + 4];
                    float wv[8] = {v0.x,v0.y,v0.z,v0.w,v1.x,v1.y,v1.z,v1.w};
                    #pragma unroll
                    for (int j = 0; j < 8; j++)
                        #pragma unroll
                        for (int i = 0; i < 8; i++)
                            acc[j][i] = fmaf(a[kw + i], wv[j], acc[j][i]);
                }
            }
        }
    }
    const int y = y0 + yy, xb = x0 + xg*8;
    #pragma unroll
    for (int j = 0; j < 8; j++) {
        int co = cg*8 + j;
        float* dst = &g_e1[((b*C1C + co) * NH + y) * NW + xb];
        float4 o0 = make_float4(fmaxf(acc[j][0],0.f), fmaxf(acc[j][1],0.f),
                                fmaxf(acc[j][2],0.f), fmaxf(acc[j][3],0.f));
        float4 o1 = make_float4(fmaxf(acc[j][4],0.f), fmaxf(acc[j][5],0.f),
                                fmaxf(acc[j][6],0.f), fmaxf(acc[j][7],0.f));
        *(float4*)dst = o0;
        *(float4*)(dst + 4) = o1;
    }
}

// ---------------------------------------------------------------------------
// conv2: 64->128, 3x3 stride 2, SAME (pad_lo=0 !), relu. out tile 8x8 on 256x256.
__global__ __launch_bounds__(256, 2)
void conv2_kernel(const float* __restrict__ wk)
{
    __shared__ __align__(16) float in_s[2][17][19];
    __shared__ __align__(16) float w_s[2][9][128];
    const int tid = threadIdx.x;
    const int xg = tid & 1, yy = (tid >> 1) & 7, cg = tid >> 4;
    const int x0 = blockIdx.x * 8, y0 = blockIdx.y * 8, b = blockIdx.z;

    float acc[8][4];
    #pragma unroll
    for (int j = 0; j < 8; j++)
        #pragma unroll
        for (int i = 0; i < 4; i++) acc[j][i] = 0.f;

    for (int c0 = 0; c0 < C1C; c0 += 2) {
        __syncthreads();
        for (int t = tid; t < 2 * 289; t += 256) {
            int ci = t / 289, rem = t - ci * 289;
            int rr = rem / 17, cx = rem - rr * 17;
            int iy = 2*y0 + rr, ix = 2*x0 + cx;   // pad_lo = 0
            float v = 0.f;
            if (iy < NH && ix < NW)
                v = g_e1[((b*C1C + c0 + ci) * NH + iy) * NW + ix];
            in_s[ci][rr][cx] = v;
        }
        for (int t = tid; t < 2 * 1152; t += 256) {
            int co = t & 127, tap = (t >> 7) % 9, ci = t / 1152;
            w_s[ci][tap][co] = wk[(co * C1C + c0 + ci) * 9 + tap];
        }
        __syncthreads();
        #pragma unroll
        for (int ci = 0; ci < 2; ci++) {
            #pragma unroll
            for (int kh = 0; kh < 3; kh++) {
                float a[9];
                #pragma unroll
                for (int c = 0; c < 9; c++) a[c] = in_s[ci][2*yy + kh][8*xg + c];
                #pragma unroll
                for (int kw = 0; kw < 3; kw++) {
                    int tap = kh*3 + kw;
                    float4 v0 = *(const float4*)&w_s[ci][tap][cg*8];
                    float4 v1 = *(const float4*)&w_s[ci][tap][cg*8 + 4];
                    float wv[8] = {v0.x,v0.y,v0.z,v0.w,v1.x,v1.y,v1.z,v1.w};
                    #pragma unroll
                    for (int j = 0; j < 8; j++)
                        #pragma unroll
                        for (int i = 0; i < 4; i++)
                            acc[j][i] = fmaf(a[2*i + kw], wv[j], acc[j][i]);
                }
            }
        }
    }
    const int y = y0 + yy, xb = x0 + xg*4;
    #pragma unroll
    for (int j = 0; j < 8; j++) {
        int co = cg*8 + j;
        float4 o = make_float4(fmaxf(acc[j][0],0.f), fmaxf(acc[j][1],0.f),
                               fmaxf(acc[j][2],0.f), fmaxf(acc[j][3],0.f));
        *(float4*)&g_d[((b*C2C + co) * (NH/2) + y) * (NW/2) + xb] = o;
    }
}

// ---------------------------------------------------------------------------
// conv3: concat(upsample(d), e1) = 192 -> 64, 3x3 SAME, relu. Tile 32x8.
__global__ __launch_bounds__(256, 2)
void conv3_kernel(const float* __restrict__ wk)
{
    __shared__ __align__(16) float in_s[4][10][35];
    __shared__ __align__(16) float w_s[4][9][64];
    const int tid = threadIdx.x;
    const int xg = tid & 3, yy = (tid >> 2) & 7, cg = tid >> 5;
    const int x0 = blockIdx.x * 32, y0 = blockIdx.y * 8, b = blockIdx.z;

    float acc[8][8];
    #pragma unroll
    for (int j = 0; j < 8; j++)
        #pragma unroll
        for (int i = 0; i < 8; i++) acc[j][i] = 0.f;

    for (int c0 = 0; c0 < C2C + C1C; c0 += 4) {
        __syncthreads();
        for (int t = tid; t < 4 * 340; t += 256) {
            int ci = t / 340, rem = t - ci * 340;
            int rr = rem / 34, cx = rem - rr * 34;
            int iy = y0 - 1 + rr, ix = x0 - 1 + cx;
            int cin = c0 + ci;
            float v = 0.f;
            if (iy >= 0 && iy < NH && ix >= 0 && ix < NW) {
                if (cin < C2C)
                    v = g_d[((b*C2C + cin) * (NH/2) + (iy >> 1)) * (NW/2) + (ix >> 1)];
                else
                    v = g_e1[((b*C1C + (cin - C2C)) * NH + iy) * NW + ix];
            }
            in_s[ci][rr][cx] = v;
        }
        for (int t = tid; t < 4 * 576; t += 256) {
            int co = t & 63, tap = (t >> 6) % 9, ci = t / 576;
            w_s[ci][tap][co] = wk[(co * (C2C + C1C) + c0 + ci) * 9 + tap];
        }
        __syncthreads();
        #pragma unroll
        for (int ci = 0; ci < 4; ci++) {
            #pragma unroll
            for (int kh = 0; kh < 3; kh++) {
                float a[10];
                #pragma unroll
                for (int c = 0; c < 10; c++) a[c] = in_s[ci][yy + kh][xg*8 + c];
                #pragma unroll
                for (int kw = 0; kw < 3; kw++) {
                    int tap = kh*3 + kw;
                    float4 v0 = *(const float4*)&w_s[ci][tap][cg*8];
                    float4 v1 = *(const float4*)&w_s[ci][tap][cg*8 + 4];
                    float wv[8] = {v0.x,v0.y,v0.z,v0.w,v1.x,v1.y,v1.z,v1.w};
                    #pragma unroll
                    for (int j = 0; j < 8; j++)
                        #pragma unroll
                        for (int i = 0; i < 8; i++)
                            acc[j][i] = fmaf(a[kw + i], wv[j], acc[j][i]);
                }
            }
        }
    }
    const int y = y0 + yy, xb = x0 + xg*8;
    #pragma unroll
    for (int j = 0; j < 8; j++) {
        int co = cg*8 + j;
        float* dst = &g_m[((b*C1C + co) * NH + y) * NW + xb];
        float4 o0 = make_float4(fmaxf(acc[j][0],0.f), fmaxf(acc[j][1],0.f),
                                fmaxf(acc[j][2],0.f), fmaxf(acc[j][3],0.f));
        float4 o1 = make_float4(fmaxf(acc[j][4],0.f), fmaxf(acc[j][5],0.f),
                                fmaxf(acc[j][6],0.f), fmaxf(acc[j][7],0.f));
        *(float4*)dst = o0;
        *(float4*)(dst + 4) = o1;
    }
}

// ---------------------------------------------------------------------------
// conv4: 64->3, 3x3 SAME, + rgb_res. out tile 64x32. thread = 8 px x 3 cout.
__global__ __launch_bounds__(256, 2)
void conv4_kernel(const float* __restrict__ wk, float* __restrict__ out)
{
    __shared__ __align__(16) float in_s[2][34][67];
    __shared__ __align__(16) float w_s[2][9][4];
    const int tid = threadIdx.x;
    const int xg = tid & 7, yy = tid >> 3;
    const int x0 = blockIdx.x * 64, y0 = blockIdx.y * 32, b = blockIdx.z;

    float acc[3][8];
    #pragma unroll
    for (int j = 0; j < 3; j++)
        #pragma unroll
        for (int i = 0; i < 8; i++) acc[j][i] = 0.f;

    for (int c0 = 0; c0 < C1C; c0 += 2) {
        __syncthreads();
        for (int t = tid; t < 2 * 34 * 66; t += 256) {
            int ci = t / 2244, rem = t - ci * 2244;
            int rr = rem / 66, cx = rem - rr * 66;
            int iy = y0 - 1 + rr, ix = x0 - 1 + cx;
            float v = 0.f;
            if (iy >= 0 && iy < NH && ix >= 0 && ix < NW)
                v = g_m[((b*C1C + c0 + ci) * NH + iy) * NW + ix];
            in_s[ci][rr][cx] = v;
        }
        if (tid < 2 * 27) {
            int ci = tid / 27, rem = tid - ci * 27;
            int co = rem % 3, tap = rem / 3;
            w_s[ci][tap][co] = wk[(co * C1C + c0 + ci) * 9 + tap];
        }
        __syncthreads();
        #pragma unroll
        for (int ci = 0; ci < 2; ci++) {
            #pragma unroll
            for (int kh = 0; kh < 3; kh++) {
                float a[10];
                #pragma unroll
                for (int c = 0; c < 10; c++) a[c] = in_s[ci][yy + kh][xg*8 + c];
                #pragma unroll
                for (int kw = 0; kw < 3; kw++) {
                    int tap = kh*3 + kw;
                    float w0v = w_s[ci][tap][0];
                    float w1v = w_s[ci][tap][1];
                    float w2v = w_s[ci][tap][2];
                    #pragma unroll
                    for (int i = 0; i < 8; i++) {
                        acc[0][i] = fmaf(a[kw + i], w0v, acc[0][i]);
                        acc[1][i] = fmaf(a[kw + i], w1v, acc[1][i]);
                        acc[2][i] = fmaf(a[kw + i], w2v, acc[2][i]);
                    }
                }
            }
        }
    }
    const int y = y0 + yy, xb = x0 + xg*8;
    #pragma unroll
    for (int j = 0; j < 3; j++) {
        int base = ((b*3 + j) * NH + y) * NW + xb;
        float4 r0 = *(const float4*)&g_rgb[base];
        float4 r1 = *(const float4*)&g_rgb[base + 4];
        // scalar stores to out (harness buffer alignment not guaranteed)
        out[base + 0] = acc[j][0] + r0.x;
        out[base + 1] = acc[j][1] + r0.y;
        out[base + 2] = acc[j][2] + r0.z;
        out[base + 3] = acc[j][3] + r0.w;
        out[base + 4] = acc[j][4] + r1.x;
        out[base + 5] = acc[j][5] + r1.y;
        out[base + 6] = acc[j][6] + r1.z;
        out[base + 7] = acc[j][7] + r1.w;
    }
}

// ---------------------------------------------------------------------------
extern "C" void kernel_launch(void* const* d_in, const int* in_sizes, int n_in,
                              void* d_out, int out_size)
{
    const float* zbuf = (const float*)d_in[0];
    const float* ray  = (const float*)d_in[1];
    // d_in[2] = gt (unused), d_in[3] = isTrain (unused)
    const float* w0 = (const float*)d_in[4];
    const float* b0 = (const float*)d_in[5];
    const float* w1 = (const float*)d_in[6];
    const float* b1 = (const float*)d_in[7];
    const float* w2 = (const float*)d_in[8];
    const float* b2 = (const float*)d_in[9];
    const float* k1 = (const float*)d_in[10];
    const float* k2 = (const float*)d_in[11];
    const float* k3 = (const float*)d_in[12];
    const float* k4 = (const float*)d_in[13];
    float* out = (float*)d_out;

    cudaFuncSetAttribute(mlp_kernel,
                         cudaFuncAttributeMaxDynamicSharedMemorySize,
                         MLP_SMEM_BYTES);

    mlp_kernel<<<(NB*NH*NW)/128, 256, MLP_SMEM_BYTES>>>(zbuf, ray,
                                                        w0, b0, w1, b1, w2, b2);
    conv1_kernel<<<dim3(NW/32, NH/8, NB), 256>>>(k1);
    conv2_kernel<<<dim3((NW/2)/8, (NH/2)/8, NB), 256>>>(k2);
    conv3_kernel<<<dim3(NW/32, NH/8, NB), 256>>>(k3);
    conv4_kernel<<<dim3(NW/64, NH/32, NB), 256>>>(k4, out);
}

// round 4
// speedup vs baseline: 1.3562x; 1.3562x over previous
#include <cuda_runtime.h>
#include <cstdint>

// Renderer_45612552684068 — round 4: conv3 (dominant, 116/177 GMAC) moved to
// tf32 mma.sync implicit GEMM. Rest unchanged from the passing fp32 R3 kernel.

static constexpr int NB   = 4;
static constexpr int NH   = 512;
static constexpr int NW   = 512;
static constexpr int HID  = 128;
static constexpr int CIN  = 29;   // DIM - 3
static constexpr int C1C  = 64;
static constexpr int C2C  = 128;

// scratch (statically allocated device globals; no cudaMalloc anywhere)
__device__ __align__(16) float g_x  [NB * CIN * NH * NW];
__device__ __align__(16) float g_rgb[NB * 3   * NH * NW];
__device__ __align__(16) float g_e1 [NB * C1C * NH * NW];
__device__ __align__(16) float g_d  [NB * C2C * (NH/2) * (NW/2)];
__device__ __align__(16) float g_m  [NB * C1C * NH * NW];

// ---------------------------------------------------------------------------
// helpers for tf32 path
__device__ __forceinline__ float tf32_rna(float x) {
    uint32_t u;
    asm("cvt.rna.tf32.f32 %0, %1;" : "=r"(u) : "f"(x));
    return __uint_as_float(u);
}

__device__ __forceinline__ void mma_tf32(float c[4],
                                         uint32_t a0, uint32_t a1,
                                         uint32_t a2, uint32_t a3,
                                         uint32_t b0, uint32_t b1) {
    asm volatile(
        "mma.sync.aligned.m16n8k8.row.col.f32.tf32.tf32.f32 "
        "{%0,%1,%2,%3}, {%4,%5,%6,%7}, {%8,%9}, {%0,%1,%2,%3};"
        : "+f"(c[0]), "+f"(c[1]), "+f"(c[2]), "+f"(c[3])
        : "r"(a0), "r"(a1), "r"(a2), "r"(a3), "r"(b0), "r"(b1));
}

// ---------------------------------------------------------------------------
// MLP kernel: 128 pixels per block, 256 threads. (unchanged, passing)
static constexpr int MLP_SMEM_FLOATS = 16384 + 16512 + 16384 + 1024 + 128 + 128;
static constexpr int MLP_SMEM_BYTES  = MLP_SMEM_FLOATS * 4;

__global__ __launch_bounds__(256, 1)
void mlp_kernel(const float* __restrict__ zbuf, const float* __restrict__ ray,
                const float* __restrict__ w0, const float* __restrict__ b0,
                const float* __restrict__ w1, const float* __restrict__ b1,
                const float* __restrict__ w2, const float* __restrict__ b2)
{
    extern __shared__ float sm[];
    float* sh_h1  = sm;
    float* sh_h2  = sh_h1 + 16384;
    float* sh_w   = sh_h2 + 16512;
    float* sh_fin = sh_w  + 16384;
    float* sh_z   = sh_fin + 1024;
    float* sh_b1  = sh_z + 128;

    const int tid   = threadIdx.x;
    const int pbase = blockIdx.x * 128;

    {
        #pragma unroll 8
        for (int t = tid; t < 16384; t += 256) sh_w[t] = w1[t];
        if (tid < 128) sh_b1[tid] = b1[tid];
    }

    if (tid < 128) {
        int pix = pbase + tid;
        int b = pix >> 18;
        int y = (pix >> 9) & 511;
        int x = pix & 511;
        int pi = (b * NH + y) * NW + x;
        float z = zbuf[pi];
        const float* r = ray + pi * 7;
        float t  = z / r[6];
        float d0 = r[3], d1 = r[4], d2 = r[5];
        sh_fin[tid * 8 + 0] = fmaf(d0, t, r[0]);
        sh_fin[tid * 8 + 1] = fmaf(d1, t, r[1]);
        sh_fin[tid * 8 + 2] = fmaf(d2, t, r[2]);
        sh_fin[tid * 8 + 3] = d0;
        sh_fin[tid * 8 + 4] = d1;
        sh_fin[tid * 8 + 5] = d2;
        sh_z[tid] = z;
    }
    __syncthreads();

    {
        const int p  = tid & 127;
        const int ob = (tid >> 7) * 64;
        float f0 = sh_fin[p*8+0], f1 = sh_fin[p*8+1], f2 = sh_fin[p*8+2];
        float f3 = sh_fin[p*8+3], f4 = sh_fin[p*8+4], f5 = sh_fin[p*8+5];
        #pragma unroll 8
        for (int o = ob; o < ob + 64; o++) {
            float acc = b0[o];
            acc = fmaf(f0, w0[0*HID + o], acc);
            acc = fmaf(f1, w0[1*HID + o], acc);
            acc = fmaf(f2, w0[2*HID + o], acc);
            acc = fmaf(f3, w0[3*HID + o], acc);
            acc = fmaf(f4, w0[4*HID + o], acc);
            acc = fmaf(f5, w0[5*HID + o], acc);
            sh_h1[o * 128 + p] = fmaxf(acc, 0.f);
        }
    }
    __syncthreads();

    const int tx = tid & 15;
    const int ty = tid >> 4;
    {
        float c[8][8];
        #pragma unroll
        for (int i = 0; i < 8; i++)
            #pragma unroll
            for (int j = 0; j < 8; j++) c[i][j] = 0.f;

        #pragma unroll 2
        for (int k = 0; k < 128; k++) {
            float a[8], bv[8];
            float4 t0 = *(const float4*)&sh_h1[k*128 + ty*8];
            float4 t1 = *(const float4*)&sh_h1[k*128 + ty*8 + 4];
            a[0]=t0.x; a[1]=t0.y; a[2]=t0.z; a[3]=t0.w;
            a[4]=t1.x; a[5]=t1.y; a[6]=t1.z; a[7]=t1.w;
            float4 u0 = *(const float4*)&sh_w[k*128 + tx*8];
            float4 u1 = *(const float4*)&sh_w[k*128 + tx*8 + 4];
            bv[0]=u0.x; bv[1]=u0.y; bv[2]=u0.z; bv[3]=u0.w;
            bv[4]=u1.x; bv[5]=u1.y; bv[6]=u1.z; bv[7]=u1.w;
            #pragma unroll
            for (int i = 0; i < 8; i++)
                #pragma unroll
                for (int j = 0; j < 8; j++)
                    c[i][j] = fmaf(a[i], bv[j], c[i][j]);
        }
        #pragma unroll
        for (int j = 0; j < 8; j++) {
            float bb = sh_b1[tx*8 + j];
            #pragma unroll
            for (int i = 0; i < 8; i++)
                sh_h2[(tx*8 + j) * 129 + (ty*8 + i)] = fmaxf(c[i][j] + bb, 0.f);
        }
    }
    __syncthreads();

    {
        for (int t = tid; t < 128*32; t += 256) sh_w[t] = w2[t];
    }
    __syncthreads();

    {
        const int p  = tid & 127;
        const int ob = (tid >> 7) * 16;
        float f[16];
        #pragma unroll
        for (int j = 0; j < 16; j++) f[j] = b2[ob + j];
        for (int k = 0; k < 128; k++) {
            float a = sh_h2[k * 129 + p];
            #pragma unroll
            for (int g = 0; g < 4; g++) {
                float4 wv = *(const float4*)&sh_w[k*32 + ob + g*4];
                f[g*4+0] = fmaf(a, wv.x, f[g*4+0]);
                f[g*4+1] = fmaf(a, wv.y, f[g*4+1]);
                f[g*4+2] = fmaf(a, wv.z, f[g*4+2]);
                f[g*4+3] = fmaf(a, wv.w, f[g*4+3]);
            }
        }
        int pix = pbase + p;
        int b = pix >> 18;
        int y = (pix >> 9) & 511;
        int x = pix & 511;
        bool mask = sh_z[p] > 0.f;
        #pragma unroll
        for (int j = 0; j < 16; j++) {
            int cch = ob + j;
            float v = mask ? f[j] : 1.0f;
            if (cch < CIN)
                g_x[((b*CIN + cch) * NH + y) * NW + x] = v;
            else
                g_rgb[((b*3 + (cch - CIN)) * NH + y) * NW + x] = v;
        }
    }
}

// ---------------------------------------------------------------------------
// conv1: 29->64, 3x3, SAME (centered), relu. (unchanged, passing)
__global__ __launch_bounds__(256, 2)
void conv1_kernel(const float* __restrict__ wk)
{
    __shared__ __align__(16) float in_s[4][10][35];
    __shared__ __align__(16) float w_s[4][9][64];
    const int tid = threadIdx.x;
    const int xg = tid & 3, yy = (tid >> 2) & 7, cg = tid >> 5;
    const int x0 = blockIdx.x * 32, y0 = blockIdx.y * 8, b = blockIdx.z;

    float acc[8][8];
    #pragma unroll
    for (int j = 0; j < 8; j++)
        #pragma unroll
        for (int i = 0; i < 8; i++) acc[j][i] = 0.f;

    for (int c0 = 0; c0 < CIN; c0 += 4) {
        const int cc = min(4, CIN - c0);
        __syncthreads();
        for (int t = tid; t < cc * 340; t += 256) {
            int ci = t / 340, rem = t - ci * 340;
            int rr = rem / 34, cx = rem - rr * 34;
            int iy = y0 - 1 + rr, ix = x0 - 1 + cx;
            float v = 0.f;
            if (iy >= 0 && iy < NH && ix >= 0 && ix < NW)
                v = g_x[((b*CIN + c0 + ci) * NH + iy) * NW + ix];
            in_s[ci][rr][cx] = v;
        }
        for (int t = tid; t < cc * 576; t += 256) {
            int co = t & 63, tap = (t >> 6) % 9, ci = t / 576;
            w_s[ci][tap][co] = wk[(co * CIN + c0 + ci) * 9 + tap];
        }
        __syncthreads();
        for (int ci = 0; ci < cc; ci++) {
            #pragma unroll
            for (int kh = 0; kh < 3; kh++) {
                float a[10];
                #pragma unroll
                for (int c = 0; c < 10; c++) a[c] = in_s[ci][yy + kh][xg*8 + c];
                #pragma unroll
                for (int kw = 0; kw < 3; kw++) {
                    int tap = kh*3 + kw;
                    float4 v0 = *(const float4*)&w_s[ci][tap][cg*8];
                    float4 v1 = *(const float4*)&w_s[ci][tap][cg*8 + 4];
                    float wv[8] = {v0.x,v0.y,v0.z,v0.w,v1.x,v1.y,v1.z,v1.w};
                    #pragma unroll
                    for (int j = 0; j < 8; j++)
                        #pragma unroll
                        for (int i = 0; i < 8; i++)
                            acc[j][i] = fmaf(a[kw + i], wv[j], acc[j][i]);
                }
            }
        }
    }
    const int y = y0 + yy, xb = x0 + xg*8;
    #pragma unroll
    for (int j = 0; j < 8; j++) {
        int co = cg*8 + j;
        float* dst = &g_e1[((b*C1C + co) * NH + y) * NW + xb];
        float4 o0 = make_float4(fmaxf(acc[j][0],0.f), fmaxf(acc[j][1],0.f),
                                fmaxf(acc[j][2],0.f), fmaxf(acc[j][3],0.f));
        float4 o1 = make_float4(fmaxf(acc[j][4],0.f), fmaxf(acc[j][5],0.f),
                                fmaxf(acc[j][6],0.f), fmaxf(acc[j][7],0.f));
        *(float4*)dst = o0;
        *(float4*)(dst + 4) = o1;
    }
}

// ---------------------------------------------------------------------------
// conv2: 64->128, 3x3 stride 2, SAME (pad_lo=0), relu. (unchanged, passing)
__global__ __launch_bounds__(256, 2)
void conv2_kernel(const float* __restrict__ wk)
{
    __shared__ __align__(16) float in_s[2][17][19];
    __shared__ __align__(16) float w_s[2][9][128];
    const int tid = threadIdx.x;
    const int xg = tid & 1, yy = (tid >> 1) & 7, cg = tid >> 4;
    const int x0 = blockIdx.x * 8, y0 = blockIdx.y * 8, b = blockIdx.z;

    float acc[8][4];
    #pragma unroll
    for (int j = 0; j < 8; j++)
        #pragma unroll
        for (int i = 0; i < 4; i++) acc[j][i] = 0.f;

    for (int c0 = 0; c0 < C1C; c0 += 2) {
        __syncthreads();
        for (int t = tid; t < 2 * 289; t += 256) {
            int ci = t / 289, rem = t - ci * 289;
            int rr = rem / 17, cx = rem - rr * 17;
            int iy = 2*y0 + rr, ix = 2*x0 + cx;
            float v = 0.f;
            if (iy < NH && ix < NW)
                v = g_e1[((b*C1C + c0 + ci) * NH + iy) * NW + ix];
            in_s[ci][rr][cx] = v;
        }
        for (int t = tid; t < 2 * 1152; t += 256) {
            int co = t & 127, tap = (t >> 7) % 9, ci = t / 1152;
            w_s[ci][tap][co] = wk[(co * C1C + c0 + ci) * 9 + tap];
        }
        __syncthreads();
        #pragma unroll
        for (int ci = 0; ci < 2; ci++) {
            #pragma unroll
            for (int kh = 0; kh < 3; kh++) {
                float a[9];
                #pragma unroll
                for (int c = 0; c < 9; c++) a[c] = in_s[ci][2*yy + kh][8*xg + c];
                #pragma unroll
                for (int kw = 0; kw < 3; kw++) {
                    int tap = kh*3 + kw;
                    float4 v0 = *(const float4*)&w_s[ci][tap][cg*8];
                    float4 v1 = *(const float4*)&w_s[ci][tap][cg*8 + 4];
                    float wv[8] = {v0.x,v0.y,v0.z,v0.w,v1.x,v1.y,v1.z,v1.w};
                    #pragma unroll
                    for (int j = 0; j < 8; j++)
                        #pragma unroll
                        for (int i = 0; i < 4; i++)
                            acc[j][i] = fmaf(a[2*i + kw], wv[j], acc[j][i]);
                }
            }
        }
    }
    const int y = y0 + yy, xb = x0 + xg*4;
    #pragma unroll
    for (int j = 0; j < 8; j++) {
        int co = cg*8 + j;
        float4 o = make_float4(fmaxf(acc[j][0],0.f), fmaxf(acc[j][1],0.f),
                               fmaxf(acc[j][2],0.f), fmaxf(acc[j][3],0.f));
        *(float4*)&g_d[((b*C2C + co) * (NH/2) + y) * (NW/2) + xb] = o;
    }
}

// ---------------------------------------------------------------------------
// conv3 (tf32 tensor-core implicit GEMM):
//   out[co, y, x] = relu( sum_{ci<192, ky, kx} W[co][ci][tap] * in[ci][y+ky-1][x+kx-1] )
//   in ci 0..127  = upsampled g_d, ci 128..191 = g_e1.
// CTA: 16x16 px tile x 64 cout, 256 threads = 8 warps; warp = 2 y-rows x 16 x x 64 co.
// K loop: 12 chunks of 16 ci; per chunk 9 taps x 2 k8-groups; mma.m16n8k8.tf32.
// smem (dynamic): in_s[16][18][20] (k-stride 360 ≡ 8 mod 32 -> conflict-free A),
//                 w_s[9][16][72]   (k-stride 72  ≡ 8 mod 32 -> conflict-free B).
static constexpr int C3_INS_CI  = 360;  // 18*20
static constexpr int C3_INS_Y   = 20;
static constexpr int C3_WS_TAP  = 1152; // 16*72
static constexpr int C3_WS_K    = 72;
static constexpr int C3_INS_FLOATS = 16 * C3_INS_CI;          // 5760
static constexpr int C3_WS_FLOATS  = 9 * C3_WS_TAP;           // 10368
static constexpr int C3_SMEM_BYTES = (C3_INS_FLOATS + C3_WS_FLOATS) * 4; // 64512

__global__ __launch_bounds__(256)
void conv3_tf32_kernel(const float* __restrict__ wk)
{
    extern __shared__ float c3sm[];
    float* in_s = c3sm;                   // [ci][yy][xx(pad20)]
    float* w_s  = c3sm + C3_INS_FLOATS;   // [tap][k][co(pad72)]

    const int tid  = threadIdx.x;
    const int w    = tid >> 5;            // warp 0..7
    const int lane = tid & 31;
    const int gid  = lane >> 2;           // 0..7
    const int tig  = lane & 3;            // 0..3

    const int x0 = blockIdx.x * 16, y0 = blockIdx.y * 16, b = blockIdx.z;

    float c[2][8][4];                     // [mt][nt][frag]
    #pragma unroll
    for (int mt = 0; mt < 2; mt++)
        #pragma unroll
        for (int nt = 0; nt < 8; nt++)
            #pragma unroll
            for (int q = 0; q < 4; q++) c[mt][nt][q] = 0.f;

    for (int ci0 = 0; ci0 < C2C + C1C; ci0 += 16) {
        __syncthreads();
        // stage input window 16ci x 18 x 18 (halo), rounded to tf32
        for (int t = tid; t < 16 * 324; t += 256) {
            int ci = t / 324; int rem = t - ci * 324;
            int yy = rem / 18, xx = rem - yy * 18;
            int iy = y0 - 1 + yy, ix = x0 - 1 + xx;
            int cin = ci0 + ci;
            float v = 0.f;
            if (iy >= 0 && iy < NH && ix >= 0 && ix < NW) {
                if (cin < C2C)
                    v = g_d[((b*C2C + cin) * (NH/2) + (iy >> 1)) * (NW/2) + (ix >> 1)];
                else
                    v = g_e1[((b*C1C + (cin - C2C)) * NH + iy) * NW + ix];
            }
            in_s[ci * C3_INS_CI + yy * C3_INS_Y + xx] = tf32_rna(v);
        }
        // stage weights 16k x 9tap x 64co, rounded to tf32
        for (int t = tid; t < 1024; t += 256) {
            int co = t & 63, k = t >> 6;
            const float* src = wk + (co * (C2C + C1C) + ci0 + k) * 9;
            #pragma unroll
            for (int tap = 0; tap < 9; tap++)
                w_s[tap * C3_WS_TAP + k * C3_WS_K + co] = tf32_rna(src[tap]);
        }
        __syncthreads();

        #pragma unroll
        for (int tap = 0; tap < 9; tap++) {
            const int ky = tap / 3, kx = tap - 3 * (tap / 3);
            #pragma unroll
            for (int g = 0; g < 2; g++) {
                const int kbase = 8 * g;
                uint32_t a[2][4];
                #pragma unroll
                for (int mt = 0; mt < 2; mt++) {
                    const int yl = 2 * w + mt;
                    const float* base0 = in_s + (kbase + tig)     * C3_INS_CI + (yl + ky) * C3_INS_Y + kx;
                    const float* base1 = in_s + (kbase + tig + 4) * C3_INS_CI + (yl + ky) * C3_INS_Y + kx;
                    a[mt][0] = __float_as_uint(base0[gid]);
                    a[mt][1] = __float_as_uint(base0[gid + 8]);
                    a[mt][2] = __float_as_uint(base1[gid]);
                    a[mt][3] = __float_as_uint(base1[gid + 8]);
                }
                const float* wb0 = w_s + tap * C3_WS_TAP + (kbase + tig)     * C3_WS_K + gid;
                const float* wb1 = w_s + tap * C3_WS_TAP + (kbase + tig + 4) * C3_WS_K + gid;
                #pragma unroll
                for (int nt = 0; nt < 8; nt++) {
                    uint32_t b0 = __float_as_uint(wb0[8 * nt]);
                    uint32_t b1 = __float_as_uint(wb1[8 * nt]);
                    mma_tf32(c[0][nt], a[0][0], a[0][1], a[0][2], a[0][3], b0, b1);
                    mma_tf32(c[1][nt], a[1][0], a[1][1], a[1][2], a[1][3], b0, b1);
                }
            }
        }
    }

    // epilogue: relu + scatter to g_m (NCHW)
    #pragma unroll
    for (int mt = 0; mt < 2; mt++) {
        const int y = y0 + 2 * w + mt;
        #pragma unroll
        for (int nt = 0; nt < 8; nt++) {
            const int co = 8 * nt + 2 * tig;
            const int x1 = x0 + gid, x2 = x0 + gid + 8;
            g_m[((b*C1C + co    ) * NH + y) * NW + x1] = fmaxf(c[mt][nt][0], 0.f);
            g_m[((b*C1C + co + 1) * NH + y) * NW + x1] = fmaxf(c[mt][nt][1], 0.f);
            g_m[((b*C1C + co    ) * NH + y) * NW + x2] = fmaxf(c[mt][nt][2], 0.f);
            g_m[((b*C1C + co + 1) * NH + y) * NW + x2] = fmaxf(c[mt][nt][3], 0.f);
        }
    }
}

// ---------------------------------------------------------------------------
// conv4: 64->3, 3x3 SAME, + rgb_res. (unchanged, passing)
__global__ __launch_bounds__(256, 2)
void conv4_kernel(const float* __restrict__ wk, float* __restrict__ out)
{
    __shared__ __align__(16) float in_s[2][34][67];
    __shared__ __align__(16) float w_s[2][9][4];
    const int tid = threadIdx.x;
    const int xg = tid & 7, yy = tid >> 3;
    const int x0 = blockIdx.x * 64, y0 = blockIdx.y * 32, b = blockIdx.z;

    float acc[3][8];
    #pragma unroll
    for (int j = 0; j < 3; j++)
        #pragma unroll
        for (int i = 0; i < 8; i++) acc[j][i] = 0.f;

    for (int c0 = 0; c0 < C1C; c0 += 2) {
        __syncthreads();
        for (int t = tid; t < 2 * 34 * 66; t += 256) {
            int ci = t / 2244, rem = t - ci * 2244;
            int rr = rem / 66, cx = rem - rr * 66;
            int iy = y0 - 1 + rr, ix = x0 - 1 + cx;
            float v = 0.f;
            if (iy >= 0 && iy < NH && ix >= 0 && ix < NW)
                v = g_m[((b*C1C + c0 + ci) * NH + iy) * NW + ix];
            in_s[ci][rr][cx] = v;
        }
        if (tid < 2 * 27) {
            int ci = tid / 27, rem = tid - ci * 27;
            int co = rem % 3, tap = rem / 3;
            w_s[ci][tap][co] = wk[(co * C1C + c0 + ci) * 9 + tap];
        }
        __syncthreads();
        #pragma unroll
        for (int ci = 0; ci < 2; ci++) {
            #pragma unroll
            for (int kh = 0; kh < 3; kh++) {
                float a[10];
                #pragma unroll
                for (int c = 0; c < 10; c++) a[c] = in_s[ci][yy + kh][xg*8 + c];
                #pragma unroll
                for (int kw = 0; kw < 3; kw++) {
                    int tap = kh*3 + kw;
                    float w0v = w_s[ci][tap][0];
                    float w1v = w_s[ci][tap][1];
                    float w2v = w_s[ci][tap][2];
                    #pragma unroll
                    for (int i = 0; i < 8; i++) {
                        acc[0][i] = fmaf(a[kw + i], w0v, acc[0][i]);
                        acc[1][i] = fmaf(a[kw + i], w1v, acc[1][i]);
                        acc[2][i] = fmaf(a[kw + i], w2v, acc[2][i]);
                    }
                }
            }
        }
    }
    const int y = y0 + yy, xb = x0 + xg*8;
    #pragma unroll
    for (int j = 0; j < 3; j++) {
        int base = ((b*3 + j) * NH + y) * NW + xb;
        float4 r0 = *(const float4*)&g_rgb[base];
        float4 r1 = *(const float4*)&g_rgb[base + 4];
        out[base + 0] = acc[j][0] + r0.x;
        out[base + 1] = acc[j][1] + r0.y;
        out[base + 2] = acc[j][2] + r0.z;
        out[base + 3] = acc[j][3] + r0.w;
        out[base + 4] = acc[j][4] + r1.x;
        out[base + 5] = acc[j][5] + r1.y;
        out[base + 6] = acc[j][6] + r1.z;
        out[base + 7] = acc[j][7] + r1.w;
    }
}

// ---------------------------------------------------------------------------
extern "C" void kernel_launch(void* const* d_in, const int* in_sizes, int n_in,
                              void* d_out, int out_size)
{
    const float* zbuf = (const float*)d_in[0];
    const float* ray  = (const float*)d_in[1];
    const float* w0 = (const float*)d_in[4];
    const float* b0 = (const float*)d_in[5];
    const float* w1 = (const float*)d_in[6];
    const float* b1 = (const float*)d_in[7];
    const float* w2 = (const float*)d_in[8];
    const float* b2 = (const float*)d_in[9];
    const float* k1 = (const float*)d_in[10];
    const float* k2 = (const float*)d_in[11];
    const float* k3 = (const float*)d_in[12];
    const float* k4 = (const float*)d_in[13];
    float* out = (float*)d_out;

    cudaFuncSetAttribute(mlp_kernel,
                         cudaFuncAttributeMaxDynamicSharedMemorySize,
                         MLP_SMEM_BYTES);
    cudaFuncSetAttribute(conv3_tf32_kernel,
                         cudaFuncAttributeMaxDynamicSharedMemorySize,
                         C3_SMEM_BYTES);

    mlp_kernel<<<(NB*NH*NW)/128, 256, MLP_SMEM_BYTES>>>(zbuf, ray,
                                                        w0, b0, w1, b1, w2, b2);
    conv1_kernel<<<dim3(NW/32, NH/8, NB), 256>>>(k1);
    conv2_kernel<<<dim3((NW/2)/8, (NH/2)/8, NB), 256>>>(k2);
    conv3_tf32_kernel<<<dim3(NW/16, NH/16, NB), 256, C3_SMEM_BYTES>>>(k3);
    conv4_kernel<<<dim3(NW/64, NH/32, NB), 256>>>(k4, out);
}